// round 13
// baseline (speedup 1.0000x reference)
#include <cuda_runtime.h>
#include <cuda_bf16.h>
#include <cstdint>

// Problem constants (B=2, S=2048, H=1024, I=2048, E=8, K=2)
#define TOKENS 4096
#define HDIM   1024
#define IDIM   2048
#define NEXP   8

// ---------------- device scratch (static globals; no runtime allocation) ----
__device__ int   g_cnt[NEXP];
__device__ int   g_off[NEXP];
__device__ int   g_tok[NEXP * TOKENS];
__device__ float g_cw [NEXP * TOKENS];
__device__ float g_probs[NEXP * TOKENS];            // [e][t]
// bf16 hi/lo splits
__device__ __align__(16) __nv_bfloat16 g_xh[TOKENS * HDIM];
__device__ __align__(16) __nv_bfloat16 g_xl[TOKENS * HDIM];
__device__ __align__(16) __nv_bfloat16 g_w1h[(size_t)NEXP * IDIM * HDIM]; // [e][i][h]
__device__ __align__(16) __nv_bfloat16 g_w1l[(size_t)NEXP * IDIM * HDIM];
__device__ __align__(16) __nv_bfloat16 g_w2h[(size_t)NEXP * IDIM * HDIM];
__device__ __align__(16) __nv_bfloat16 g_w2l[(size_t)NEXP * IDIM * HDIM];
__device__ __align__(16) __nv_bfloat16 g_w3h[(size_t)NEXP * HDIM * IDIM]; // [e][h][i]
__device__ __align__(16) __nv_bfloat16 g_w3l[(size_t)NEXP * HDIM * IDIM];
// hidden activations (rows grouped by expert), bf16 hi/lo
__device__ __align__(16) __nv_bfloat16 g_hh[(size_t)(2 * TOKENS) * IDIM];
__device__ __align__(16) __nv_bfloat16 g_hl[(size_t)(2 * TOKENS) * IDIM];

// ---------------- helpers -----------------------------------------------------
__device__ __forceinline__ uint32_t smem_u32(const void* p) {
    uint32_t a;
    asm("{ .reg .u64 t; cvta.to.shared.u64 t, %1; cvt.u32.u64 %0, t; }"
        : "=r"(a) : "l"(p));
    return a;
}

__device__ __forceinline__ void cpasync(uint32_t s, const void* g) {
    asm volatile("cp.async.cg.shared.global [%0], [%1], 16;"
                 :: "r"(s), "l"(g));
}
#define CP_COMMIT asm volatile("cp.async.commit_group;" ::: "memory")
#define CP_WAIT1  asm volatile("cp.async.wait_group 1;" ::: "memory")

__device__ __forceinline__ void ldm4(uint32_t* r, uint32_t addr) {
    asm volatile("ldmatrix.sync.aligned.m8n8.x4.shared.b16 {%0,%1,%2,%3}, [%4];"
                 : "=r"(r[0]), "=r"(r[1]), "=r"(r[2]), "=r"(r[3]) : "r"(addr));
}

__device__ __forceinline__ void mma16816(float* c, const uint32_t* a,
                                         const uint32_t* b) {
    asm volatile(
        "mma.sync.aligned.m16n8k16.row.col.f32.bf16.bf16.f32 "
        "{%0,%1,%2,%3},{%4,%5,%6,%7},{%8,%9},{%0,%1,%2,%3};"
        : "+f"(c[0]), "+f"(c[1]), "+f"(c[2]), "+f"(c[3])
        : "r"(a[0]), "r"(a[1]), "r"(a[2]), "r"(a[3]), "r"(b[0]), "r"(b[1]));
}

__device__ __forceinline__ void split2(float v, unsigned short& h, unsigned short& l) {
    __nv_bfloat16 bh = __float2bfloat16_rn(v);
    float r = v - __bfloat162float(bh);
    __nv_bfloat16 bl = __float2bfloat16_rn(r);
    h = __bfloat16_as_ushort(bh);
    l = __bfloat16_as_ushort(bl);
}

// ---------------- tiny kernels ------------------------------------------------
__global__ void init_kernel() {
    int i = threadIdx.x;
    if (i < NEXP) g_cnt[i] = 0;
}

__global__ void offsets_kernel() {
    int s = 0;
    for (int e = 0; e < NEXP; e++) { g_off[e] = s; s += g_cnt[e]; }
}

// ---------------- router -------------------------------------------------------
__global__ void router_kernel(const float* __restrict__ x,
                              const float* __restrict__ Wr) {
    int t    = blockIdx.x * 4 + (threadIdx.x >> 5);
    int lane = threadIdx.x & 31;
    const float* xr = x + (size_t)t * HDIM;

    float acc[NEXP];
#pragma unroll
    for (int e = 0; e < NEXP; e++) acc[e] = 0.f;

    for (int h = lane; h < HDIM; h += 32) {
        float xv = xr[h];
        const float* w = Wr + h * NEXP;
#pragma unroll
        for (int e = 0; e < NEXP; e++) acc[e] += xv * w[e];
    }
#pragma unroll
    for (int e = 0; e < NEXP; e++) {
#pragma unroll
        for (int o = 16; o; o >>= 1)
            acc[e] += __shfl_xor_sync(0xffffffffu, acc[e], o);
    }

    if (lane == 0) {
        float mx = acc[0];
#pragma unroll
        for (int e = 1; e < NEXP; e++) mx = fmaxf(mx, acc[e]);
        float p[NEXP];
        float s = 0.f;
#pragma unroll
        for (int e = 0; e < NEXP; e++) { p[e] = expf(acc[e] - mx); s += p[e]; }
        float inv = 1.f / s;
#pragma unroll
        for (int e = 0; e < NEXP; e++) {
            p[e] *= inv;
            g_probs[e * TOKENS + t] = p[e];
        }
        int i1 = 0; float p1 = p[0];
#pragma unroll
        for (int e = 1; e < NEXP; e++) if (p[e] > p1) { p1 = p[e]; i1 = e; }
        int i2 = -1; float p2 = -1.f;
#pragma unroll
        for (int e = 0; e < NEXP; e++)
            if (e != i1 && p[e] > p2) { p2 = p[e]; i2 = e; }
        float winv = 1.f / (p1 + p2);

        int pos1 = atomicAdd(&g_cnt[i1], 1);
        g_tok[i1 * TOKENS + pos1] = t;
        g_cw [i1 * TOKENS + pos1] = p1 * winv;
        int pos2 = atomicAdd(&g_cnt[i2], 1);
        g_tok[i2 * TOKENS + pos2] = t;
        g_cw [i2 * TOKENS + pos2] = p2 * winv;
    }
}

// ---------------- aux loss -----------------------------------------------------
__global__ void aux_kernel(float* __restrict__ out, int aux_idx) {
    __shared__ float sh[256];
    int tid = threadIdx.x;
    float a[NEXP];
#pragma unroll
    for (int e = 0; e < NEXP; e++) a[e] = 0.f;
    for (int t = tid; t < TOKENS; t += 256) {
#pragma unroll
        for (int e = 0; e < NEXP; e++) a[e] += g_probs[e * TOKENS + t];
    }
    float loss = 0.f;
    for (int e = 0; e < NEXP; e++) {
        sh[tid] = a[e];
        __syncthreads();
        for (int s = 128; s; s >>= 1) {
            if (tid < s) sh[tid] += sh[tid + s];
            __syncthreads();
        }
        if (tid == 0) {
            float u = sh[0] * (1.f / TOKENS) - (1.f / NEXP);
            loss += u * u;
        }
        __syncthreads();
    }
    if (tid == 0) out[aux_idx] = loss * 0.01f;
}

// ---------------- conversions --------------------------------------------------
__global__ void convx_kernel(const float* __restrict__ x) {
    int i = blockIdx.x * 256 + threadIdx.x;   // float4 index
    float4 v = ((const float4*)x)[i];
    unsigned short h0, l0, h1, l1, h2, l2, h3, l3;
    split2(v.x, h0, l0); split2(v.y, h1, l1);
    split2(v.z, h2, l2); split2(v.w, h3, l3);
    ((uint2*)g_xh)[i] = make_uint2((unsigned)h0 | ((unsigned)h1 << 16),
                                   (unsigned)h2 | ((unsigned)h3 << 16));
    ((uint2*)g_xl)[i] = make_uint2((unsigned)l0 | ((unsigned)l1 << 16),
                                   (unsigned)l2 | ((unsigned)l3 << 16));
}

// transpose + bf16-split: src fp32 [e][R][C] -> dst bf16 [e][C][R].
// IMPORTANT: destination device globals are selected INSIDE device code by
// `which` (0=w1, 1=w2, 2=w3) — passing __device__ symbols from host is UB.
__global__ void trconv_kernel(const float* __restrict__ src, int which,
                              int R, int C) {
    __nv_bfloat16* dh;
    __nv_bfloat16* dl;
    if (which == 0)      { dh = g_w1h; dl = g_w1l; }
    else if (which == 1) { dh = g_w2h; dl = g_w2l; }
    else                 { dh = g_w3h; dl = g_w3l; }

    __shared__ float tile[32][33];
    const size_t eo = (size_t)blockIdx.z * R * C;
    src += eo; dh += eo; dl += eo;
    int c0 = blockIdx.x * 32, r0 = blockIdx.y * 32;
    int tx = threadIdx.x, ty = threadIdx.y;
#pragma unroll
    for (int j = 0; j < 4; j++)
        tile[ty + 8 * j][tx] = src[(size_t)(r0 + ty + 8 * j) * C + c0 + tx];
    __syncthreads();
#pragma unroll
    for (int j = 0; j < 4; j++) {
        float v = tile[tx][ty + 8 * j];
        unsigned short h, l; split2(v, h, l);
        size_t di = (size_t)(c0 + ty + 8 * j) * R + r0 + tx;
        dh[di] = __ushort_as_bfloat16(h);
        dl[di] = __ushort_as_bfloat16(l);
    }
}

// =============================================================================
// GEMM kernels: bf16 mma.sync, extended-K error-compensated split
// (Ah*Bh + Al*Bh + Ah*Bl). 128x64 CTA tiles, k=32 stages, double-buffered
// cp.async, static shared memory (<48KB).
// SMEM rows padded to 80B: ldmatrix conflict-free (banks 20r mod 32).
// =============================================================================

#define G1_STAGE 20480   // (128 A + 64 B1 + 64 B2) rows * 80B
#define G2_STAGE 15360   // (128 A + 64 B)          rows * 80B

// GEMM1: h = silu(Xg @ w1^T) * (Xg @ w2^T). K_eff = 3*HDIM = 3072 -> 96 stages.
__global__ void __launch_bounds__(256) moe_gemm1() {
    __shared__ __align__(128) unsigned char smem[2 * G1_STAGE];
    const int e   = blockIdx.z;
    const int cnt = g_cnt[e];
    const int m0  = blockIdx.x * 128;
    if (m0 >= cnt) return;
    const int n0  = blockIdx.y * 64;
    const int off = g_off[e];
    const int tid = threadIdx.x;
    const int lane = tid & 31, wid = tid >> 5;
    const int wm = (wid & 3) * 32, wn = (wid >> 2) * 32;
    const uint32_t sb = smem_u32(smem);

    // A loader: row = tid>>1 (0..127), two 16B chunks
    const int arow = tid >> 1;
    const int ac0  = (tid & 1) * 2;
    const size_t atok = (size_t)g_tok[e * TOKENS + min(m0 + arow, cnt - 1)] * HDIM;
    // B loader: row = tid>>2 (0..63), one 16B chunk per matrix
    const int brow = tid >> 2;
    const int bch  = tid & 3;
    const size_t boff = ((size_t)e * IDIM + (n0 + brow)) * HDIM;
    const uint32_t asrow = (uint32_t)arow * 80;
    const uint32_t bsrow = (uint32_t)brow * 80 + (uint32_t)bch * 16;

    auto load_stage = [&](int kb, int slot) {
        const int sel = kb >> 5;                 // 0:Ah*Bh 1:Al*Bh 2:Ah*Bl
        const int k0  = (kb & 31) * 32;
        const __nv_bfloat16* ax = (sel == 1) ? g_xl  : g_xh;
        const __nv_bfloat16* b1 = (sel == 2) ? g_w1l : g_w1h;
        const __nv_bfloat16* b2 = (sel == 2) ? g_w2l : g_w2h;
        const uint32_t s = sb + slot * G1_STAGE;
        cpasync(s + asrow + (ac0 + 0) * 16, ax + atok + k0 + (ac0 + 0) * 8);
        cpasync(s + asrow + (ac0 + 1) * 16, ax + atok + k0 + (ac0 + 1) * 8);
        cpasync(s + 10240 + bsrow, b1 + boff + k0 + bch * 8);
        cpasync(s + 15360 + bsrow, b2 + boff + k0 + bch * 8);
    };

    float cg[32], cu[32];
#pragma unroll
    for (int i = 0; i < 32; i++) { cg[i] = 0.f; cu[i] = 0.f; }

    const uint32_t aoffL = (lane & 15) * 80 + (lane >> 4) * 16;
    const uint32_t boffL = ((lane & 7) + ((lane >> 4) & 1) * 8) * 80 +
                           ((lane >> 3) & 1) * 16;

    auto compute = [&](int slot) {
        const uint32_t s   = sb + slot * G1_STAGE;
        const uint32_t aB  = s + (uint32_t)wm * 80 + aoffL;
        const uint32_t b1B = s + 10240 + (uint32_t)wn * 80 + boffL;
        const uint32_t b2B = s + 15360 + (uint32_t)wn * 80 + boffL;
#pragma unroll
        for (int k16 = 0; k16 < 2; k16++) {
            uint32_t a[2][4];
#pragma unroll
            for (int i = 0; i < 2; i++)
                ldm4(a[i], aB + i * 16 * 80 + k16 * 32);
            uint32_t bg[4][2], bu[4][2];
#pragma unroll
            for (int jj = 0; jj < 2; jj++) {
                uint32_t r[4];
                ldm4(r, b1B + jj * 16 * 80 + k16 * 32);
                bg[2*jj][0] = r[0]; bg[2*jj][1] = r[1];
                bg[2*jj+1][0] = r[2]; bg[2*jj+1][1] = r[3];
                ldm4(r, b2B + jj * 16 * 80 + k16 * 32);
                bu[2*jj][0] = r[0]; bu[2*jj][1] = r[1];
                bu[2*jj+1][0] = r[2]; bu[2*jj+1][1] = r[3];
            }
#pragma unroll
            for (int i = 0; i < 2; i++)
#pragma unroll
                for (int j = 0; j < 4; j++) {
                    mma16816(&cg[(i * 4 + j) * 4], a[i], bg[j]);
                    mma16816(&cu[(i * 4 + j) * 4], a[i], bu[j]);
                }
        }
    };

    load_stage(0, 0);
    CP_COMMIT;
    for (int kb = 0; kb < 96; kb++) {
        const int nk = kb + 1;
        if (nk < 96) load_stage(nk, nk & 1);
        CP_COMMIT;                 // one commit per iteration (empty ok)
        CP_WAIT1;                  // stage kb complete
        __syncthreads();
        compute(kb & 1);
        __syncthreads();
    }

    // epilogue: h = silu(g)*u, bf16 split, store
#pragma unroll
    for (int i = 0; i < 2; i++)
#pragma unroll
        for (int j = 0; j < 4; j++) {
            const float* cgp = &cg[(i * 4 + j) * 4];
            const float* cup = &cu[(i * 4 + j) * 4];
            const int mA = m0 + wm + i * 16 + (lane >> 2);
            const int n  = n0 + wn + j * 8 + (lane & 3) * 2;
#pragma unroll
            for (int hlf = 0; hlf < 2; hlf++) {
                const int mm = mA + hlf * 8;
                if (mm < cnt) {
                    float g0 = cgp[hlf * 2], g1 = cgp[hlf * 2 + 1];
                    float u0 = cup[hlf * 2], u1 = cup[hlf * 2 + 1];
                    float v0 = (g0 / (1.f + expf(-g0))) * u0;
                    float v1 = (g1 / (1.f + expf(-g1))) * u1;
                    unsigned short h0, l0, h1, l1;
                    split2(v0, h0, l0);
                    split2(v1, h1, l1);
                    size_t di = (size_t)(off + mm) * IDIM + n;
                    *(uint32_t*)(g_hh + di) = (unsigned)h0 | ((unsigned)h1 << 16);
                    *(uint32_t*)(g_hl + di) = (unsigned)l0 | ((unsigned)l1 << 16);
                }
            }
        }
}

// GEMM2: out[tok] += cw * (H_e @ w3^T). K_eff = 3*IDIM = 6144 -> 192 stages.
__global__ void __launch_bounds__(256) moe_gemm2(float* __restrict__ out) {
    __shared__ __align__(128) unsigned char smem[2 * G2_STAGE];
    const int e   = blockIdx.z;
    const int cnt = g_cnt[e];
    const int m0  = blockIdx.x * 128;
    if (m0 >= cnt) return;
    const int n0  = blockIdx.y * 64;
    const int off = g_off[e];
    const int tid = threadIdx.x;
    const int lane = tid & 31, wid = tid >> 5;
    const int wm = (wid & 3) * 32, wn = (wid >> 2) * 32;
    const uint32_t sb = smem_u32(smem);

    const int arow = tid >> 1;
    const int ac0  = (tid & 1) * 2;
    const size_t aoff = (size_t)(off + min(m0 + arow, cnt - 1)) * IDIM;
    const int brow = tid >> 2;
    const int bch  = tid & 3;
    const size_t boff = ((size_t)e * HDIM + (n0 + brow)) * IDIM;
    const uint32_t asrow = (uint32_t)arow * 80;
    const uint32_t bsrow = (uint32_t)brow * 80 + (uint32_t)bch * 16;

    auto load_stage = [&](int kb, int slot) {
        const int sel = kb >> 6;                 // 0,1,2
        const int k0  = (kb & 63) * 32;
        const __nv_bfloat16* ax = (sel == 1) ? g_hl  : g_hh;
        const __nv_bfloat16* bx = (sel == 2) ? g_w3l : g_w3h;
        const uint32_t s = sb + slot * G2_STAGE;
        cpasync(s + asrow + (ac0 + 0) * 16, ax + aoff + k0 + (ac0 + 0) * 8);
        cpasync(s + asrow + (ac0 + 1) * 16, ax + aoff + k0 + (ac0 + 1) * 8);
        cpasync(s + 10240 + bsrow, bx + boff + k0 + bch * 8);
    };

    float cc[32];
#pragma unroll
    for (int i = 0; i < 32; i++) cc[i] = 0.f;

    const uint32_t aoffL = (lane & 15) * 80 + (lane >> 4) * 16;
    const uint32_t boffL = ((lane & 7) + ((lane >> 4) & 1) * 8) * 80 +
                           ((lane >> 3) & 1) * 16;

    auto compute = [&](int slot) {
        const uint32_t s  = sb + slot * G2_STAGE;
        const uint32_t aB = s + (uint32_t)wm * 80 + aoffL;
        const uint32_t bB = s + 10240 + (uint32_t)wn * 80 + boffL;
#pragma unroll
        for (int k16 = 0; k16 < 2; k16++) {
            uint32_t a[2][4];
#pragma unroll
            for (int i = 0; i < 2; i++)
                ldm4(a[i], aB + i * 16 * 80 + k16 * 32);
            uint32_t bb[4][2];
#pragma unroll
            for (int jj = 0; jj < 2; jj++) {
                uint32_t r[4];
                ldm4(r, bB + jj * 16 * 80 + k16 * 32);
                bb[2*jj][0] = r[0]; bb[2*jj][1] = r[1];
                bb[2*jj+1][0] = r[2]; bb[2*jj+1][1] = r[3];
            }
#pragma unroll
            for (int i = 0; i < 2; i++)
#pragma unroll
                for (int j = 0; j < 4; j++)
                    mma16816(&cc[(i * 4 + j) * 4], a[i], bb[j]);
        }
    };

    load_stage(0, 0);
    CP_COMMIT;
    for (int kb = 0; kb < 192; kb++) {
        const int nk = kb + 1;
        if (nk < 192) load_stage(nk, nk & 1);
        CP_COMMIT;
        CP_WAIT1;
        __syncthreads();
        compute(kb & 1);
        __syncthreads();
    }

    // epilogue: weighted atomic scatter (2 commutative adds per out element)
#pragma unroll
    for (int i = 0; i < 2; i++)
#pragma unroll
        for (int j = 0; j < 4; j++) {
            const float* cp = &cc[(i * 4 + j) * 4];
            const int mA = m0 + wm + i * 16 + (lane >> 2);
            const int n  = n0 + wn + j * 8 + (lane & 3) * 2;
#pragma unroll
            for (int hlf = 0; hlf < 2; hlf++) {
                const int mm = mA + hlf * 8;
                if (mm < cnt) {
                    int   tok = g_tok[e * TOKENS + mm];
                    float cw  = g_cw [e * TOKENS + mm];
                    float* op = out + (size_t)tok * HDIM + n;
                    atomicAdd(op + 0, cw * cp[hlf * 2 + 0]);
                    atomicAdd(op + 1, cw * cp[hlf * 2 + 1]);
                }
            }
        }
}

// ---------------- launch --------------------------------------------------------
extern "C" void kernel_launch(void* const* d_in, const int* in_sizes, int n_in,
                              void* d_out, int out_size) {
    const float* x  = (const float*)d_in[0];
    const float* Wr = (const float*)d_in[1];
    const float* w1 = (const float*)d_in[2];
    const float* w2 = (const float*)d_in[3];
    const float* w3 = (const float*)d_in[4];
    float* out = (float*)d_out;

    cudaMemsetAsync(d_out, 0, (size_t)out_size * sizeof(float));
    init_kernel<<<1, 32>>>();
    router_kernel<<<TOKENS / 4, 128>>>(x, Wr);
    offsets_kernel<<<1, 1>>>();
    aux_kernel<<<1, 256>>>(out, out_size - 1);
    convx_kernel<<<TOKENS * HDIM / 4 / 256, 256>>>(x);
    trconv_kernel<<<dim3(IDIM / 32, HDIM / 32, NEXP), dim3(32, 8)>>>(w1, 0, HDIM, IDIM);
    trconv_kernel<<<dim3(IDIM / 32, HDIM / 32, NEXP), dim3(32, 8)>>>(w2, 1, HDIM, IDIM);
    trconv_kernel<<<dim3(HDIM / 32, IDIM / 32, NEXP), dim3(32, 8)>>>(w3, 2, IDIM, HDIM);
    moe_gemm1<<<dim3(TOKENS / 128, IDIM / 64, NEXP), 256>>>();
    moe_gemm2<<<dim3(TOKENS / 128, HDIM / 64, NEXP), 256>>>(out);
}

// round 14
// speedup vs baseline: 1.0339x; 1.0339x over previous
#include <cuda_runtime.h>
#include <cuda_bf16.h>
#include <cstdint>

// Problem constants (B=2, S=2048, H=1024, I=2048, E=8, K=2)
#define TOKENS 4096
#define HDIM   1024
#define IDIM   2048
#define NEXP   8

// ---------------- device scratch (static globals; no runtime allocation) ----
__device__ int   g_cnt[NEXP];
__device__ int   g_off[NEXP];
__device__ int   g_tok[NEXP * TOKENS];
__device__ float g_cw [NEXP * TOKENS];
__device__ float g_probs[NEXP * TOKENS];            // [e][t]
// bf16 hi/lo splits
__device__ __align__(16) __nv_bfloat16 g_xh[TOKENS * HDIM];
__device__ __align__(16) __nv_bfloat16 g_xl[TOKENS * HDIM];
__device__ __align__(16) __nv_bfloat16 g_w1h[(size_t)NEXP * IDIM * HDIM]; // [e][i][h]
__device__ __align__(16) __nv_bfloat16 g_w1l[(size_t)NEXP * IDIM * HDIM];
__device__ __align__(16) __nv_bfloat16 g_w2h[(size_t)NEXP * IDIM * HDIM];
__device__ __align__(16) __nv_bfloat16 g_w2l[(size_t)NEXP * IDIM * HDIM];
__device__ __align__(16) __nv_bfloat16 g_w3h[(size_t)NEXP * HDIM * IDIM]; // [e][h][i]
__device__ __align__(16) __nv_bfloat16 g_w3l[(size_t)NEXP * HDIM * IDIM];
// hidden activations (rows grouped by expert), bf16 hi/lo
__device__ __align__(16) __nv_bfloat16 g_hh[(size_t)(2 * TOKENS) * IDIM];
__device__ __align__(16) __nv_bfloat16 g_hl[(size_t)(2 * TOKENS) * IDIM];

// ---------------- helpers -----------------------------------------------------
__device__ __forceinline__ uint32_t smem_u32(const void* p) {
    uint32_t a;
    asm("{ .reg .u64 t; cvta.to.shared.u64 t, %1; cvt.u32.u64 %0, t; }"
        : "=r"(a) : "l"(p));
    return a;
}

__device__ __forceinline__ void cpasync(uint32_t s, const void* g) {
    asm volatile("cp.async.cg.shared.global [%0], [%1], 16;"
                 :: "r"(s), "l"(g));
}
#define CP_COMMIT asm volatile("cp.async.commit_group;" ::: "memory")
#define CP_WAIT1  asm volatile("cp.async.wait_group 1;" ::: "memory")

__device__ __forceinline__ void ldm4(uint32_t* r, uint32_t addr) {
    asm volatile("ldmatrix.sync.aligned.m8n8.x4.shared.b16 {%0,%1,%2,%3}, [%4];"
                 : "=r"(r[0]), "=r"(r[1]), "=r"(r[2]), "=r"(r[3]) : "r"(addr));
}

__device__ __forceinline__ void mma16816(float* c, const uint32_t* a,
                                         const uint32_t* b) {
    asm volatile(
        "mma.sync.aligned.m16n8k16.row.col.f32.bf16.bf16.f32 "
        "{%0,%1,%2,%3},{%4,%5,%6,%7},{%8,%9},{%0,%1,%2,%3};"
        : "+f"(c[0]), "+f"(c[1]), "+f"(c[2]), "+f"(c[3])
        : "r"(a[0]), "r"(a[1]), "r"(a[2]), "r"(a[3]), "r"(b[0]), "r"(b[1]));
}

__device__ __forceinline__ void split2(float v, unsigned short& h, unsigned short& l) {
    __nv_bfloat16 bh = __float2bfloat16_rn(v);
    float r = v - __bfloat162float(bh);
    __nv_bfloat16 bl = __float2bfloat16_rn(r);
    h = __bfloat16_as_ushort(bh);
    l = __bfloat16_as_ushort(bl);
}

// ---------------- tiny kernels ------------------------------------------------
__global__ void init_kernel() {
    int i = threadIdx.x;
    if (i < NEXP) g_cnt[i] = 0;
}

__global__ void offsets_kernel() {
    int s = 0;
    for (int e = 0; e < NEXP; e++) { g_off[e] = s; s += g_cnt[e]; }
}

// ---------------- router -------------------------------------------------------
__global__ void router_kernel(const float* __restrict__ x,
                              const float* __restrict__ Wr) {
    int t    = blockIdx.x * 4 + (threadIdx.x >> 5);
    int lane = threadIdx.x & 31;
    const float* xr = x + (size_t)t * HDIM;

    float acc[NEXP];
#pragma unroll
    for (int e = 0; e < NEXP; e++) acc[e] = 0.f;

    for (int h = lane; h < HDIM; h += 32) {
        float xv = xr[h];
        const float* w = Wr + h * NEXP;
#pragma unroll
        for (int e = 0; e < NEXP; e++) acc[e] += xv * w[e];
    }
#pragma unroll
    for (int e = 0; e < NEXP; e++) {
#pragma unroll
        for (int o = 16; o; o >>= 1)
            acc[e] += __shfl_xor_sync(0xffffffffu, acc[e], o);
    }

    if (lane == 0) {
        float mx = acc[0];
#pragma unroll
        for (int e = 1; e < NEXP; e++) mx = fmaxf(mx, acc[e]);
        float p[NEXP];
        float s = 0.f;
#pragma unroll
        for (int e = 0; e < NEXP; e++) { p[e] = expf(acc[e] - mx); s += p[e]; }
        float inv = 1.f / s;
#pragma unroll
        for (int e = 0; e < NEXP; e++) {
            p[e] *= inv;
            g_probs[e * TOKENS + t] = p[e];
        }
        int i1 = 0; float p1 = p[0];
#pragma unroll
        for (int e = 1; e < NEXP; e++) if (p[e] > p1) { p1 = p[e]; i1 = e; }
        int i2 = -1; float p2 = -1.f;
#pragma unroll
        for (int e = 0; e < NEXP; e++)
            if (e != i1 && p[e] > p2) { p2 = p[e]; i2 = e; }
        float winv = 1.f / (p1 + p2);

        int pos1 = atomicAdd(&g_cnt[i1], 1);
        g_tok[i1 * TOKENS + pos1] = t;
        g_cw [i1 * TOKENS + pos1] = p1 * winv;
        int pos2 = atomicAdd(&g_cnt[i2], 1);
        g_tok[i2 * TOKENS + pos2] = t;
        g_cw [i2 * TOKENS + pos2] = p2 * winv;
    }
}

// ---------------- aux loss -----------------------------------------------------
__global__ void aux_kernel(float* __restrict__ out, int aux_idx) {
    __shared__ float sh[256];
    int tid = threadIdx.x;
    float a[NEXP];
#pragma unroll
    for (int e = 0; e < NEXP; e++) a[e] = 0.f;
    for (int t = tid; t < TOKENS; t += 256) {
#pragma unroll
        for (int e = 0; e < NEXP; e++) a[e] += g_probs[e * TOKENS + t];
    }
    float loss = 0.f;
    for (int e = 0; e < NEXP; e++) {
        sh[tid] = a[e];
        __syncthreads();
        for (int s = 128; s; s >>= 1) {
            if (tid < s) sh[tid] += sh[tid + s];
            __syncthreads();
        }
        if (tid == 0) {
            float u = sh[0] * (1.f / TOKENS) - (1.f / NEXP);
            loss += u * u;
        }
        __syncthreads();
    }
    if (tid == 0) out[aux_idx] = loss * 0.01f;
}

// ---------------- conversions --------------------------------------------------
__global__ void convx_kernel(const float* __restrict__ x) {
    int i = blockIdx.x * 256 + threadIdx.x;   // float4 index
    float4 v = ((const float4*)x)[i];
    unsigned short h0, l0, h1, l1, h2, l2, h3, l3;
    split2(v.x, h0, l0); split2(v.y, h1, l1);
    split2(v.z, h2, l2); split2(v.w, h3, l3);
    ((uint2*)g_xh)[i] = make_uint2((unsigned)h0 | ((unsigned)h1 << 16),
                                   (unsigned)h2 | ((unsigned)h3 << 16));
    ((uint2*)g_xl)[i] = make_uint2((unsigned)l0 | ((unsigned)l1 << 16),
                                   (unsigned)l2 | ((unsigned)l3 << 16));
}

// transpose + bf16-split: src fp32 [e][R][C] -> dst bf16 [e][C][R].
// Destination globals selected INSIDE device code by `which`.
__global__ void trconv_kernel(const float* __restrict__ src, int which,
                              int R, int C) {
    __nv_bfloat16* dh;
    __nv_bfloat16* dl;
    if (which == 0)      { dh = g_w1h; dl = g_w1l; }
    else if (which == 1) { dh = g_w2h; dl = g_w2l; }
    else                 { dh = g_w3h; dl = g_w3l; }

    __shared__ float tile[32][33];
    const size_t eo = (size_t)blockIdx.z * R * C;
    src += eo; dh += eo; dl += eo;
    int c0 = blockIdx.x * 32, r0 = blockIdx.y * 32;
    int tx = threadIdx.x, ty = threadIdx.y;
#pragma unroll
    for (int j = 0; j < 4; j++)
        tile[ty + 8 * j][tx] = src[(size_t)(r0 + ty + 8 * j) * C + c0 + tx];
    __syncthreads();
#pragma unroll
    for (int j = 0; j < 4; j++) {
        float v = tile[tx][ty + 8 * j];
        unsigned short h, l; split2(v, h, l);
        size_t di = (size_t)(c0 + ty + 8 * j) * R + r0 + tx;
        dh[di] = __ushort_as_bfloat16(h);
        dl[di] = __ushort_as_bfloat16(l);
    }
}

// =============================================================================
// GEMMs: bf16 mma.sync, 3-term split (Ah*Bh + Al*Bh + Ah*Bl) with UNIFIED k16
// stages: all operand versions co-resident, each loaded exactly once per
// k-block. Row pitch 48B (k=16): conflict-free ldmatrix (banks 12r mod 32
// distinct over 8 rows), 16B-aligned for cp.async. Double-buffered, 48KB
// static SMEM.
// =============================================================================

#define G_STAGE 24576    // 512 rows * 48B

// GEMM1: h = silu(Xg @ w1^T) * (Xg @ w2^T). CTA 128(M) x 64(N), 64 stages.
// SMEM rows: [0,128) Ah | [128,256) Al | [256,320) B1h | [320,384) B1l
//            | [384,448) B2h | [448,512) B2l
__global__ void __launch_bounds__(256) moe_gemm1() {
    __shared__ __align__(128) unsigned char smem[2 * G_STAGE];   // 49152
    const int e   = blockIdx.z;
    const int cnt = g_cnt[e];
    const int m0  = blockIdx.x * 128;
    if (m0 >= cnt) return;
    const int n0  = blockIdx.y * 64;
    const int off = g_off[e];
    const int tid = threadIdx.x;
    const int lane = tid & 31, wid = tid >> 5;
    const int wm = (wid & 3) * 32, wn = (wid >> 2) * 32;
    const uint32_t sb = smem_u32(smem);

    // A loader: thread -> one A row (0..127 = hi, 128..255 = lo), 32B
    const int ar = tid & 127;
    const size_t atok = (size_t)g_tok[e * TOKENS + min(m0 + ar, cnt - 1)] * HDIM;
    const __nv_bfloat16* asrc = ((tid < 128) ? g_xh : g_xl) + atok;
    // B loader: thread -> one B row; version v = tid>>6 (w1h,w1l,w2h,w2l)
    const int bv = tid >> 6, br = tid & 63;
    const size_t bo = ((size_t)e * IDIM + (n0 + br)) * HDIM;
    const __nv_bfloat16* bsrc =
        (bv == 0 ? g_w1h : bv == 1 ? g_w1l : bv == 2 ? g_w2h : g_w2l) + bo;
    const uint32_t arow = (uint32_t)tid * 48;
    const uint32_t brow = 12288u + (uint32_t)tid * 48;

    auto load_stage = [&](int s, int slot) {
        const int k0 = s * 16;
        const uint32_t b = sb + slot * G_STAGE;
        cpasync(b + arow +  0, asrc + k0);
        cpasync(b + arow + 16, asrc + k0 + 8);
        cpasync(b + brow +  0, bsrc + k0);
        cpasync(b + brow + 16, bsrc + k0 + 8);
    };

    float cg[32], cu[32];
#pragma unroll
    for (int i = 0; i < 32; i++) { cg[i] = 0.f; cu[i] = 0.f; }

    const uint32_t aoffL = (lane & 15) * 48 + (lane >> 4) * 16;
    const uint32_t boffL = ((lane & 7) + ((lane >> 4) & 1) * 8) * 48 +
                           ((lane >> 3) & 1) * 16;

    auto ldb = [&](uint32_t vb, uint32_t bf[4][2]) {
        uint32_t r[4];
        ldm4(r, vb);
        bf[0][0] = r[0]; bf[0][1] = r[1]; bf[1][0] = r[2]; bf[1][1] = r[3];
        ldm4(r, vb + 16 * 48);
        bf[2][0] = r[0]; bf[2][1] = r[1]; bf[3][0] = r[2]; bf[3][1] = r[3];
    };

    auto compute = [&](int slot) {
        const uint32_t s  = sb + slot * G_STAGE;
        const uint32_t aH = s + (uint32_t)wm * 48 + aoffL;
        const uint32_t bB = s + 12288u + (uint32_t)wn * 48 + boffL;
        uint32_t ah[2][4], al[2][4];
        ldm4(ah[0], aH);            ldm4(ah[1], aH + 16 * 48);
        ldm4(al[0], aH + 6144);     ldm4(al[1], aH + 6144 + 16 * 48);
        uint32_t bf[4][2];
        ldb(bB, bf);                       // B1h: Ah + Al terms
#pragma unroll
        for (int i = 0; i < 2; i++)
#pragma unroll
            for (int j = 0; j < 4; j++) {
                mma16816(&cg[(i * 4 + j) * 4], ah[i], bf[j]);
                mma16816(&cg[(i * 4 + j) * 4], al[i], bf[j]);
            }
        ldb(bB + 3072, bf);                // B1l: Ah term
#pragma unroll
        for (int i = 0; i < 2; i++)
#pragma unroll
            for (int j = 0; j < 4; j++)
                mma16816(&cg[(i * 4 + j) * 4], ah[i], bf[j]);
        ldb(bB + 6144, bf);                // B2h: Ah + Al terms
#pragma unroll
        for (int i = 0; i < 2; i++)
#pragma unroll
            for (int j = 0; j < 4; j++) {
                mma16816(&cu[(i * 4 + j) * 4], ah[i], bf[j]);
                mma16816(&cu[(i * 4 + j) * 4], al[i], bf[j]);
            }
        ldb(bB + 9216, bf);                // B2l: Ah term
#pragma unroll
        for (int i = 0; i < 2; i++)
#pragma unroll
            for (int j = 0; j < 4; j++)
                mma16816(&cu[(i * 4 + j) * 4], ah[i], bf[j]);
    };

    load_stage(0, 0);
    CP_COMMIT;
    for (int kb = 0; kb < 64; kb++) {
        const int nk = kb + 1;
        if (nk < 64) load_stage(nk, nk & 1);
        CP_COMMIT;
        CP_WAIT1;
        __syncthreads();
        compute(kb & 1);
        __syncthreads();
    }

    // epilogue: h = silu(g)*u, bf16 split, store
#pragma unroll
    for (int i = 0; i < 2; i++)
#pragma unroll
        for (int j = 0; j < 4; j++) {
            const float* cgp = &cg[(i * 4 + j) * 4];
            const float* cup = &cu[(i * 4 + j) * 4];
            const int mA = m0 + wm + i * 16 + (lane >> 2);
            const int n  = n0 + wn + j * 8 + (lane & 3) * 2;
#pragma unroll
            for (int hlf = 0; hlf < 2; hlf++) {
                const int mm = mA + hlf * 8;
                if (mm < cnt) {
                    float g0 = cgp[hlf * 2], g1 = cgp[hlf * 2 + 1];
                    float u0 = cup[hlf * 2], u1 = cup[hlf * 2 + 1];
                    float v0 = (g0 / (1.f + expf(-g0))) * u0;
                    float v1 = (g1 / (1.f + expf(-g1))) * u1;
                    unsigned short h0, l0, h1, l1;
                    split2(v0, h0, l0);
                    split2(v1, h1, l1);
                    size_t di = (size_t)(off + mm) * IDIM + n;
                    *(uint32_t*)(g_hh + di) = (unsigned)h0 | ((unsigned)h1 << 16);
                    *(uint32_t*)(g_hl + di) = (unsigned)l0 | ((unsigned)l1 << 16);
                }
            }
        }
}

// GEMM2: out[tok] += cw * (H_e @ w3^T). CTA 128(M) x 128(N), 128 stages.
// SMEM rows: [0,128) Ah | [128,256) Al | [256,384) Bh | [384,512) Bl
__global__ void __launch_bounds__(256) moe_gemm2(float* __restrict__ out) {
    __shared__ __align__(128) unsigned char smem[2 * G_STAGE];   // 49152
    const int e   = blockIdx.z;
    const int cnt = g_cnt[e];
    const int m0  = blockIdx.x * 128;
    if (m0 >= cnt) return;
    const int n0  = blockIdx.y * 128;
    const int off = g_off[e];
    const int tid = threadIdx.x;
    const int lane = tid & 31, wid = tid >> 5;
    const int wm = (wid & 3) * 32, wn = (wid >> 2) * 64;
    const uint32_t sb = smem_u32(smem);

    const int ar = tid & 127;
    const size_t aoff = (size_t)(off + min(m0 + ar, cnt - 1)) * IDIM;
    const __nv_bfloat16* asrc = ((tid < 128) ? g_hh : g_hl) + aoff;
    const int bv = tid >> 7, br = tid & 127;
    const size_t bo = ((size_t)e * HDIM + (n0 + br)) * IDIM;
    const __nv_bfloat16* bsrc = (bv ? g_w3l : g_w3h) + bo;
    const uint32_t arow = (uint32_t)tid * 48;
    const uint32_t brow = 12288u + (uint32_t)tid * 48;

    auto load_stage = [&](int s, int slot) {
        const int k0 = s * 16;
        const uint32_t b = sb + slot * G_STAGE;
        cpasync(b + arow +  0, asrc + k0);
        cpasync(b + arow + 16, asrc + k0 + 8);
        cpasync(b + brow +  0, bsrc + k0);
        cpasync(b + brow + 16, bsrc + k0 + 8);
    };

    float cc[64];
#pragma unroll
    for (int i = 0; i < 64; i++) cc[i] = 0.f;

    const uint32_t aoffL = (lane & 15) * 48 + (lane >> 4) * 16;
    const uint32_t boffL = ((lane & 7) + ((lane >> 4) & 1) * 8) * 48 +
                           ((lane >> 3) & 1) * 16;

    auto ldb8 = [&](uint32_t vb, uint32_t bf[8][2]) {
#pragma unroll
        for (int jj = 0; jj < 4; jj++) {
            uint32_t r[4];
            ldm4(r, vb + jj * 16 * 48);
            bf[2 * jj][0] = r[0]; bf[2 * jj][1] = r[1];
            bf[2 * jj + 1][0] = r[2]; bf[2 * jj + 1][1] = r[3];
        }
    };

    auto compute = [&](int slot) {
        const uint32_t s  = sb + slot * G_STAGE;
        const uint32_t aH = s + (uint32_t)wm * 48 + aoffL;
        const uint32_t bB = s + 12288u + (uint32_t)wn * 48 + boffL;
        uint32_t ah[2][4], al[2][4];
        ldm4(ah[0], aH);            ldm4(ah[1], aH + 16 * 48);
        ldm4(al[0], aH + 6144);     ldm4(al[1], aH + 6144 + 16 * 48);
        uint32_t bf[8][2];
        ldb8(bB, bf);                      // Bh: Ah + Al terms
#pragma unroll
        for (int i = 0; i < 2; i++)
#pragma unroll
            for (int j = 0; j < 8; j++) {
                mma16816(&cc[(i * 8 + j) * 4], ah[i], bf[j]);
                mma16816(&cc[(i * 8 + j) * 4], al[i], bf[j]);
            }
        ldb8(bB + 6144, bf);               // Bl: Ah term
#pragma unroll
        for (int i = 0; i < 2; i++)
#pragma unroll
            for (int j = 0; j < 8; j++)
                mma16816(&cc[(i * 8 + j) * 4], ah[i], bf[j]);
    };

    load_stage(0, 0);
    CP_COMMIT;
    for (int kb = 0; kb < 128; kb++) {
        const int nk = kb + 1;
        if (nk < 128) load_stage(nk, nk & 1);
        CP_COMMIT;
        CP_WAIT1;
        __syncthreads();
        compute(kb & 1);
        __syncthreads();
    }

    // epilogue: weighted atomic scatter (2 commutative adds per out element)
#pragma unroll
    for (int i = 0; i < 2; i++)
#pragma unroll
        for (int j = 0; j < 8; j++) {
            const float* cp = &cc[(i * 8 + j) * 4];
            const int mA = m0 + wm + i * 16 + (lane >> 2);
            const int n  = n0 + wn + j * 8 + (lane & 3) * 2;
#pragma unroll
            for (int hlf = 0; hlf < 2; hlf++) {
                const int mm = mA + hlf * 8;
                if (mm < cnt) {
                    int   tok = g_tok[e * TOKENS + mm];
                    float cw  = g_cw [e * TOKENS + mm];
                    float* op = out + (size_t)tok * HDIM + n;
                    atomicAdd(op + 0, cw * cp[hlf * 2 + 0]);
                    atomicAdd(op + 1, cw * cp[hlf * 2 + 1]);
                }
            }
        }
}

// ---------------- launch --------------------------------------------------------
extern "C" void kernel_launch(void* const* d_in, const int* in_sizes, int n_in,
                              void* d_out, int out_size) {
    const float* x  = (const float*)d_in[0];
    const float* Wr = (const float*)d_in[1];
    const float* w1 = (const float*)d_in[2];
    const float* w2 = (const float*)d_in[3];
    const float* w3 = (const float*)d_in[4];
    float* out = (float*)d_out;

    cudaMemsetAsync(d_out, 0, (size_t)out_size * sizeof(float));
    init_kernel<<<1, 32>>>();
    router_kernel<<<TOKENS / 4, 128>>>(x, Wr);
    offsets_kernel<<<1, 1>>>();
    aux_kernel<<<1, 256>>>(out, out_size - 1);
    convx_kernel<<<TOKENS * HDIM / 4 / 256, 256>>>(x);
    trconv_kernel<<<dim3(IDIM / 32, HDIM / 32, NEXP), dim3(32, 8)>>>(w1, 0, HDIM, IDIM);
    trconv_kernel<<<dim3(IDIM / 32, HDIM / 32, NEXP), dim3(32, 8)>>>(w2, 1, HDIM, IDIM);
    trconv_kernel<<<dim3(HDIM / 32, IDIM / 32, NEXP), dim3(32, 8)>>>(w3, 2, IDIM, HDIM);
    moe_gemm1<<<dim3(TOKENS / 128, IDIM / 64, NEXP), 256>>>();
    moe_gemm2<<<dim3(TOKENS / 128, HDIM / 128, NEXP), 256>>>(out);
}

// round 15
// speedup vs baseline: 1.0356x; 1.0016x over previous
#include <cuda_runtime.h>
#include <cuda_bf16.h>
#include <cstdint>

// Problem constants (B=2, S=2048, H=1024, I=2048, E=8, K=2)
#define TOKENS 4096
#define HDIM   1024
#define IDIM   2048
#define NEXP   8

// ---------------- device scratch (static globals; no runtime allocation) ----
__device__ int   g_cnt[NEXP];
__device__ int   g_off[NEXP];
__device__ int   g_tok[NEXP * TOKENS];
__device__ float g_cw [NEXP * TOKENS];
__device__ float g_probs[NEXP * TOKENS];            // [e][t]
// bf16 hi/lo splits
__device__ __align__(16) __nv_bfloat16 g_xh[TOKENS * HDIM];
__device__ __align__(16) __nv_bfloat16 g_xl[TOKENS * HDIM];
__device__ __align__(16) __nv_bfloat16 g_w1h[(size_t)NEXP * IDIM * HDIM]; // [e][i][h]
__device__ __align__(16) __nv_bfloat16 g_w1l[(size_t)NEXP * IDIM * HDIM];
__device__ __align__(16) __nv_bfloat16 g_w2h[(size_t)NEXP * IDIM * HDIM];
__device__ __align__(16) __nv_bfloat16 g_w2l[(size_t)NEXP * IDIM * HDIM];
__device__ __align__(16) __nv_bfloat16 g_w3h[(size_t)NEXP * HDIM * IDIM]; // [e][h][i]
__device__ __align__(16) __nv_bfloat16 g_w3l[(size_t)NEXP * HDIM * IDIM];
// hidden activations (rows grouped by expert), bf16 hi/lo
__device__ __align__(16) __nv_bfloat16 g_hh[(size_t)(2 * TOKENS) * IDIM];
__device__ __align__(16) __nv_bfloat16 g_hl[(size_t)(2 * TOKENS) * IDIM];

// ---------------- helpers -----------------------------------------------------
__device__ __forceinline__ uint32_t smem_u32(const void* p) {
    uint32_t a;
    asm("{ .reg .u64 t; cvta.to.shared.u64 t, %1; cvt.u32.u64 %0, t; }"
        : "=r"(a) : "l"(p));
    return a;
}

__device__ __forceinline__ void cpasync(uint32_t s, const void* g) {
    asm volatile("cp.async.cg.shared.global [%0], [%1], 16;"
                 :: "r"(s), "l"(g));
}
#define CP_COMMIT asm volatile("cp.async.commit_group;" ::: "memory")
#define CP_WAIT1  asm volatile("cp.async.wait_group 1;" ::: "memory")

__device__ __forceinline__ void ldm4(uint32_t* r, uint32_t addr) {
    asm volatile("ldmatrix.sync.aligned.m8n8.x4.shared.b16 {%0,%1,%2,%3}, [%4];"
                 : "=r"(r[0]), "=r"(r[1]), "=r"(r[2]), "=r"(r[3]) : "r"(addr));
}

__device__ __forceinline__ void mma16816(float* c, const uint32_t* a,
                                         const uint32_t* b) {
    asm volatile(
        "mma.sync.aligned.m16n8k16.row.col.f32.bf16.bf16.f32 "
        "{%0,%1,%2,%3},{%4,%5,%6,%7},{%8,%9},{%0,%1,%2,%3};"
        : "+f"(c[0]), "+f"(c[1]), "+f"(c[2]), "+f"(c[3])
        : "r"(a[0]), "r"(a[1]), "r"(a[2]), "r"(a[3]), "r"(b[0]), "r"(b[1]));
}

__device__ __forceinline__ void split2(float v, unsigned short& h, unsigned short& l) {
    __nv_bfloat16 bh = __float2bfloat16_rn(v);
    float r = v - __bfloat162float(bh);
    __nv_bfloat16 bl = __float2bfloat16_rn(r);
    h = __bfloat16_as_ushort(bh);
    l = __bfloat16_as_ushort(bl);
}

// ---------------- tiny kernels ------------------------------------------------
__global__ void init_kernel() {
    int i = threadIdx.x;
    if (i < NEXP) g_cnt[i] = 0;
}

__global__ void offsets_kernel() {
    int s = 0;
    for (int e = 0; e < NEXP; e++) { g_off[e] = s; s += g_cnt[e]; }
}

// ---------------- router -------------------------------------------------------
__global__ void router_kernel(const float* __restrict__ x,
                              const float* __restrict__ Wr) {
    int t    = blockIdx.x * 4 + (threadIdx.x >> 5);
    int lane = threadIdx.x & 31;
    const float* xr = x + (size_t)t * HDIM;

    float acc[NEXP];
#pragma unroll
    for (int e = 0; e < NEXP; e++) acc[e] = 0.f;

    for (int h = lane; h < HDIM; h += 32) {
        float xv = xr[h];
        const float* w = Wr + h * NEXP;
#pragma unroll
        for (int e = 0; e < NEXP; e++) acc[e] += xv * w[e];
    }
#pragma unroll
    for (int e = 0; e < NEXP; e++) {
#pragma unroll
        for (int o = 16; o; o >>= 1)
            acc[e] += __shfl_xor_sync(0xffffffffu, acc[e], o);
    }

    if (lane == 0) {
        float mx = acc[0];
#pragma unroll
        for (int e = 1; e < NEXP; e++) mx = fmaxf(mx, acc[e]);
        float p[NEXP];
        float s = 0.f;
#pragma unroll
        for (int e = 0; e < NEXP; e++) { p[e] = expf(acc[e] - mx); s += p[e]; }
        float inv = 1.f / s;
#pragma unroll
        for (int e = 0; e < NEXP; e++) {
            p[e] *= inv;
            g_probs[e * TOKENS + t] = p[e];
        }
        int i1 = 0; float p1 = p[0];
#pragma unroll
        for (int e = 1; e < NEXP; e++) if (p[e] > p1) { p1 = p[e]; i1 = e; }
        int i2 = -1; float p2 = -1.f;
#pragma unroll
        for (int e = 0; e < NEXP; e++)
            if (e != i1 && p[e] > p2) { p2 = p[e]; i2 = e; }
        float winv = 1.f / (p1 + p2);

        int pos1 = atomicAdd(&g_cnt[i1], 1);
        g_tok[i1 * TOKENS + pos1] = t;
        g_cw [i1 * TOKENS + pos1] = p1 * winv;
        int pos2 = atomicAdd(&g_cnt[i2], 1);
        g_tok[i2 * TOKENS + pos2] = t;
        g_cw [i2 * TOKENS + pos2] = p2 * winv;
    }
}

// ---------------- aux loss -----------------------------------------------------
__global__ void aux_kernel(float* __restrict__ out, int aux_idx) {
    __shared__ float sh[256];
    int tid = threadIdx.x;
    float a[NEXP];
#pragma unroll
    for (int e = 0; e < NEXP; e++) a[e] = 0.f;
    for (int t = tid; t < TOKENS; t += 256) {
#pragma unroll
        for (int e = 0; e < NEXP; e++) a[e] += g_probs[e * TOKENS + t];
    }
    float loss = 0.f;
    for (int e = 0; e < NEXP; e++) {
        sh[tid] = a[e];
        __syncthreads();
        for (int s = 128; s; s >>= 1) {
            if (tid < s) sh[tid] += sh[tid + s];
            __syncthreads();
        }
        if (tid == 0) {
            float u = sh[0] * (1.f / TOKENS) - (1.f / NEXP);
            loss += u * u;
        }
        __syncthreads();
    }
    if (tid == 0) out[aux_idx] = loss * 0.01f;
}

// ---------------- conversions --------------------------------------------------
__global__ void convx_kernel(const float* __restrict__ x) {
    int i = blockIdx.x * 256 + threadIdx.x;   // float4 index
    float4 v = ((const float4*)x)[i];
    unsigned short h0, l0, h1, l1, h2, l2, h3, l3;
    split2(v.x, h0, l0); split2(v.y, h1, l1);
    split2(v.z, h2, l2); split2(v.w, h3, l3);
    ((uint2*)g_xh)[i] = make_uint2((unsigned)h0 | ((unsigned)h1 << 16),
                                   (unsigned)h2 | ((unsigned)h3 << 16));
    ((uint2*)g_xl)[i] = make_uint2((unsigned)l0 | ((unsigned)l1 << 16),
                                   (unsigned)l2 | ((unsigned)l3 << 16));
}

// transpose + bf16-split: src fp32 [e][R][C] -> dst bf16 [e][C][R].
// Destination globals selected INSIDE device code by `which`.
__global__ void trconv_kernel(const float* __restrict__ src, int which,
                              int R, int C) {
    __nv_bfloat16* dh;
    __nv_bfloat16* dl;
    if (which == 0)      { dh = g_w1h; dl = g_w1l; }
    else if (which == 1) { dh = g_w2h; dl = g_w2l; }
    else                 { dh = g_w3h; dl = g_w3l; }

    __shared__ float tile[32][33];
    const size_t eo = (size_t)blockIdx.z * R * C;
    src += eo; dh += eo; dl += eo;
    int c0 = blockIdx.x * 32, r0 = blockIdx.y * 32;
    int tx = threadIdx.x, ty = threadIdx.y;
#pragma unroll
    for (int j = 0; j < 4; j++)
        tile[ty + 8 * j][tx] = src[(size_t)(r0 + ty + 8 * j) * C + c0 + tx];
    __syncthreads();
#pragma unroll
    for (int j = 0; j < 4; j++) {
        float v = tile[tx][ty + 8 * j];
        unsigned short h, l; split2(v, h, l);
        size_t di = (size_t)(c0 + ty + 8 * j) * R + r0 + tx;
        dh[di] = __ushort_as_bfloat16(h);
        dl[di] = __ushort_as_bfloat16(l);
    }
}

// =============================================================================
// GEMMs: bf16 mma.sync, 3-term split (Ah*Bh + Al*Bh + Ah*Bl) with UNIFIED k16
// stages: all operand versions co-resident, each loaded exactly once per
// k-block. Row pitch 48B (k=16): conflict-free ldmatrix (banks 12r mod 32
// distinct over 8 rows), 16B-aligned for cp.async. Double-buffered, 48KB
// static SMEM.
// =============================================================================

#define G_STAGE 24576    // 512 rows * 48B

// GEMM1: h = silu(Xg @ w1^T) * (Xg @ w2^T). CTA 128(M) x 64(N), 64 stages.
// SMEM rows: [0,128) Ah | [128,256) Al | [256,320) B1h | [320,384) B1l
//            | [384,448) B2h | [448,512) B2l
__global__ void __launch_bounds__(256) moe_gemm1() {
    __shared__ __align__(128) unsigned char smem[2 * G_STAGE];   // 49152
    const int e   = blockIdx.z;
    const int cnt = g_cnt[e];
    const int m0  = blockIdx.x * 128;
    if (m0 >= cnt) return;
    const int n0  = blockIdx.y * 64;
    const int off = g_off[e];
    const int tid = threadIdx.x;
    const int lane = tid & 31, wid = tid >> 5;
    const int wm = (wid & 3) * 32, wn = (wid >> 2) * 32;
    const uint32_t sb = smem_u32(smem);

    // A loader: thread -> one A row (0..127 = hi, 128..255 = lo), 32B
    const int ar = tid & 127;
    const size_t atok = (size_t)g_tok[e * TOKENS + min(m0 + ar, cnt - 1)] * HDIM;
    const __nv_bfloat16* asrc = ((tid < 128) ? g_xh : g_xl) + atok;
    // B loader: thread -> one B row; version v = tid>>6 (w1h,w1l,w2h,w2l)
    const int bv = tid >> 6, br = tid & 63;
    const size_t bo = ((size_t)e * IDIM + (n0 + br)) * HDIM;
    const __nv_bfloat16* bsrc =
        (bv == 0 ? g_w1h : bv == 1 ? g_w1l : bv == 2 ? g_w2h : g_w2l) + bo;
    const uint32_t arow = (uint32_t)tid * 48;
    const uint32_t brow = 12288u + (uint32_t)tid * 48;

    auto load_stage = [&](int s, int slot) {
        const int k0 = s * 16;
        const uint32_t b = sb + slot * G_STAGE;
        cpasync(b + arow +  0, asrc + k0);
        cpasync(b + arow + 16, asrc + k0 + 8);
        cpasync(b + brow +  0, bsrc + k0);
        cpasync(b + brow + 16, bsrc + k0 + 8);
    };

    float cg[32], cu[32];
#pragma unroll
    for (int i = 0; i < 32; i++) { cg[i] = 0.f; cu[i] = 0.f; }

    const uint32_t aoffL = (lane & 15) * 48 + (lane >> 4) * 16;
    const uint32_t boffL = ((lane & 7) + ((lane >> 4) & 1) * 8) * 48 +
                           ((lane >> 3) & 1) * 16;

    auto ldb = [&](uint32_t vb, uint32_t bf[4][2]) {
        uint32_t r[4];
        ldm4(r, vb);
        bf[0][0] = r[0]; bf[0][1] = r[1]; bf[1][0] = r[2]; bf[1][1] = r[3];
        ldm4(r, vb + 16 * 48);
        bf[2][0] = r[0]; bf[2][1] = r[1]; bf[3][0] = r[2]; bf[3][1] = r[3];
    };

    auto compute = [&](int slot) {
        const uint32_t s  = sb + slot * G_STAGE;
        const uint32_t aH = s + (uint32_t)wm * 48 + aoffL;
        const uint32_t bB = s + 12288u + (uint32_t)wn * 48 + boffL;
        uint32_t ah[2][4], al[2][4];
        ldm4(ah[0], aH);            ldm4(ah[1], aH + 16 * 48);
        ldm4(al[0], aH + 6144);     ldm4(al[1], aH + 6144 + 16 * 48);
        uint32_t bf[4][2];
        ldb(bB, bf);                       // B1h: Ah + Al terms
#pragma unroll
        for (int i = 0; i < 2; i++)
#pragma unroll
            for (int j = 0; j < 4; j++) {
                mma16816(&cg[(i * 4 + j) * 4], ah[i], bf[j]);
                mma16816(&cg[(i * 4 + j) * 4], al[i], bf[j]);
            }
        ldb(bB + 3072, bf);                // B1l: Ah term
#pragma unroll
        for (int i = 0; i < 2; i++)
#pragma unroll
            for (int j = 0; j < 4; j++)
                mma16816(&cg[(i * 4 + j) * 4], ah[i], bf[j]);
        ldb(bB + 6144, bf);                // B2h: Ah + Al terms
#pragma unroll
        for (int i = 0; i < 2; i++)
#pragma unroll
            for (int j = 0; j < 4; j++) {
                mma16816(&cu[(i * 4 + j) * 4], ah[i], bf[j]);
                mma16816(&cu[(i * 4 + j) * 4], al[i], bf[j]);
            }
        ldb(bB + 9216, bf);                // B2l: Ah term
#pragma unroll
        for (int i = 0; i < 2; i++)
#pragma unroll
            for (int j = 0; j < 4; j++)
                mma16816(&cu[(i * 4 + j) * 4], ah[i], bf[j]);
    };

    load_stage(0, 0);
    CP_COMMIT;
    for (int kb = 0; kb < 64; kb++) {
        const int nk = kb + 1;
        if (nk < 64) load_stage(nk, nk & 1);
        CP_COMMIT;
        CP_WAIT1;
        __syncthreads();
        compute(kb & 1);
        __syncthreads();
    }

    // epilogue: h = silu(g)*u, bf16 split, store
#pragma unroll
    for (int i = 0; i < 2; i++)
#pragma unroll
        for (int j = 0; j < 4; j++) {
            const float* cgp = &cg[(i * 4 + j) * 4];
            const float* cup = &cu[(i * 4 + j) * 4];
            const int mA = m0 + wm + i * 16 + (lane >> 2);
            const int n  = n0 + wn + j * 8 + (lane & 3) * 2;
#pragma unroll
            for (int hlf = 0; hlf < 2; hlf++) {
                const int mm = mA + hlf * 8;
                if (mm < cnt) {
                    float g0 = cgp[hlf * 2], g1 = cgp[hlf * 2 + 1];
                    float u0 = cup[hlf * 2], u1 = cup[hlf * 2 + 1];
                    float v0 = (g0 / (1.f + expf(-g0))) * u0;
                    float v1 = (g1 / (1.f + expf(-g1))) * u1;
                    unsigned short h0, l0, h1, l1;
                    split2(v0, h0, l0);
                    split2(v1, h1, l1);
                    size_t di = (size_t)(off + mm) * IDIM + n;
                    *(uint32_t*)(g_hh + di) = (unsigned)h0 | ((unsigned)h1 << 16);
                    *(uint32_t*)(g_hl + di) = (unsigned)l0 | ((unsigned)l1 << 16);
                }
            }
        }
}

// GEMM2: out[tok] += cw * (H_e @ w3^T). CTA 128(M) x 128(N), 128 stages.
// SMEM rows: [0,128) Ah | [128,256) Al | [256,384) Bh | [384,512) Bl
__global__ void __launch_bounds__(256) moe_gemm2(float* __restrict__ out) {
    __shared__ __align__(128) unsigned char smem[2 * G_STAGE];   // 49152
    const int e   = blockIdx.z;
    const int cnt = g_cnt[e];
    const int m0  = blockIdx.x * 128;
    if (m0 >= cnt) return;
    const int n0  = blockIdx.y * 128;
    const int off = g_off[e];
    const int tid = threadIdx.x;
    const int lane = tid & 31, wid = tid >> 5;
    const int wm = (wid & 3) * 32, wn = (wid >> 2) * 64;
    const uint32_t sb = smem_u32(smem);

    const int ar = tid & 127;
    const size_t aoff = (size_t)(off + min(m0 + ar, cnt - 1)) * IDIM;
    const __nv_bfloat16* asrc = ((tid < 128) ? g_hh : g_hl) + aoff;
    const int bv = tid >> 7, br = tid & 127;
    const size_t bo = ((size_t)e * HDIM + (n0 + br)) * IDIM;
    const __nv_bfloat16* bsrc = (bv ? g_w3l : g_w3h) + bo;
    const uint32_t arow = (uint32_t)tid * 48;
    const uint32_t brow = 12288u + (uint32_t)tid * 48;

    auto load_stage = [&](int s, int slot) {
        const int k0 = s * 16;
        const uint32_t b = sb + slot * G_STAGE;
        cpasync(b + arow +  0, asrc + k0);
        cpasync(b + arow + 16, asrc + k0 + 8);
        cpasync(b + brow +  0, bsrc + k0);
        cpasync(b + brow + 16, bsrc + k0 + 8);
    };

    float cc[64];
#pragma unroll
    for (int i = 0; i < 64; i++) cc[i] = 0.f;

    const uint32_t aoffL = (lane & 15) * 48 + (lane >> 4) * 16;
    const uint32_t boffL = ((lane & 7) + ((lane >> 4) & 1) * 8) * 48 +
                           ((lane >> 3) & 1) * 16;

    auto ldb8 = [&](uint32_t vb, uint32_t bf[8][2]) {
#pragma unroll
        for (int jj = 0; jj < 4; jj++) {
            uint32_t r[4];
            ldm4(r, vb + jj * 16 * 48);
            bf[2 * jj][0] = r[0]; bf[2 * jj][1] = r[1];
            bf[2 * jj + 1][0] = r[2]; bf[2 * jj + 1][1] = r[3];
        }
    };

    auto compute = [&](int slot) {
        const uint32_t s  = sb + slot * G_STAGE;
        const uint32_t aH = s + (uint32_t)wm * 48 + aoffL;
        const uint32_t bB = s + 12288u + (uint32_t)wn * 48 + boffL;
        uint32_t ah[2][4], al[2][4];
        ldm4(ah[0], aH);            ldm4(ah[1], aH + 16 * 48);
        ldm4(al[0], aH + 6144);     ldm4(al[1], aH + 6144 + 16 * 48);
        uint32_t bf[8][2];
        ldb8(bB, bf);                      // Bh: Ah + Al terms
#pragma unroll
        for (int i = 0; i < 2; i++)
#pragma unroll
            for (int j = 0; j < 8; j++) {
                mma16816(&cc[(i * 8 + j) * 4], ah[i], bf[j]);
                mma16816(&cc[(i * 8 + j) * 4], al[i], bf[j]);
            }
        ldb8(bB + 6144, bf);               // Bl: Ah term
#pragma unroll
        for (int i = 0; i < 2; i++)
#pragma unroll
            for (int j = 0; j < 8; j++)
                mma16816(&cc[(i * 8 + j) * 4], ah[i], bf[j]);
    };

    load_stage(0, 0);
    CP_COMMIT;
    for (int kb = 0; kb < 128; kb++) {
        const int nk = kb + 1;
        if (nk < 128) load_stage(nk, nk & 1);
        CP_COMMIT;
        CP_WAIT1;
        __syncthreads();
        compute(kb & 1);
        __syncthreads();
    }

    // epilogue: weighted atomic scatter (2 commutative adds per out element)
#pragma unroll
    for (int i = 0; i < 2; i++)
#pragma unroll
        for (int j = 0; j < 8; j++) {
            const float* cp = &cc[(i * 8 + j) * 4];
            const int mA = m0 + wm + i * 16 + (lane >> 2);
            const int n  = n0 + wn + j * 8 + (lane & 3) * 2;
#pragma unroll
            for (int hlf = 0; hlf < 2; hlf++) {
                const int mm = mA + hlf * 8;
                if (mm < cnt) {
                    int   tok = g_tok[e * TOKENS + mm];
                    float cw  = g_cw [e * TOKENS + mm];
                    float* op = out + (size_t)tok * HDIM + n;
                    atomicAdd(op + 0, cw * cp[hlf * 2 + 0]);
                    atomicAdd(op + 1, cw * cp[hlf * 2 + 1]);
                }
            }
        }
}

// ---------------- launch --------------------------------------------------------
extern "C" void kernel_launch(void* const* d_in, const int* in_sizes, int n_in,
                              void* d_out, int out_size) {
    const float* x  = (const float*)d_in[0];
    const float* Wr = (const float*)d_in[1];
    const float* w1 = (const float*)d_in[2];
    const float* w2 = (const float*)d_in[3];
    const float* w3 = (const float*)d_in[4];
    float* out = (float*)d_out;

    cudaMemsetAsync(d_out, 0, (size_t)out_size * sizeof(float));
    init_kernel<<<1, 32>>>();
    router_kernel<<<TOKENS / 4, 128>>>(x, Wr);
    offsets_kernel<<<1, 1>>>();
    aux_kernel<<<1, 256>>>(out, out_size - 1);
    convx_kernel<<<TOKENS * HDIM / 4 / 256, 256>>>(x);
    trconv_kernel<<<dim3(IDIM / 32, HDIM / 32, NEXP), dim3(32, 8)>>>(w1, 0, HDIM, IDIM);
    trconv_kernel<<<dim3(IDIM / 32, HDIM / 32, NEXP), dim3(32, 8)>>>(w2, 1, HDIM, IDIM);
    trconv_kernel<<<dim3(HDIM / 32, IDIM / 32, NEXP), dim3(32, 8)>>>(w3, 2, IDIM, HDIM);
    moe_gemm1<<<dim3(TOKENS / 128, IDIM / 64, NEXP), 256>>>();
    moe_gemm2<<<dim3(TOKENS / 128, HDIM / 128, NEXP), 256>>>(out);
}